// round 12
// baseline (speedup 1.0000x reference)
#include <cuda_runtime.h>
#include <math.h>

#define NB 64
#define IMG 224
#define HP 110
#define NPIX (IMG*IMG)
#define HG 320
#define WG 640

typedef unsigned long long ull;

// ---------------- scratch ----------------------------------------------------
__device__ float  g_xs[(size_t)NB * 3 * NPIX];        // x shifted by one element
__device__ float  g_h1[(size_t)NB * 6 * HP * HP];
__device__ float  g_startf[NB], g_dlogf[NB];
__device__ float  g_radii[NB * HG];
__device__ float  g_unit[WG * 2];

// ---------------- f32x2 helpers ----------------------------------------------
__device__ __forceinline__ ull pk(float lo, float hi) {
    ull r; asm("mov.b64 %0,{%1,%2};" : "=l"(r) : "f"(lo), "f"(hi)); return r;
}
__device__ __forceinline__ float2 unpk(ull v) {
    float2 r; asm("mov.b64 {%0,%1},%2;" : "=f"(r.x), "=f"(r.y) : "l"(v)); return r;
}
__device__ __forceinline__ void fma2(ull& d, ull a, ull b) {
    asm("fma.rn.f32x2 %0,%1,%2,%0;" : "+l"(d) : "l"(a), "l"(b));
}

// ---------------- K1: xs[i] = x[i+1] shift + unit table ----------------------
__global__ void k_shift_unit(const float* __restrict__ x) {
    int blk = blockIdx.x;
    if (blk >= 9408) {                     // unit-table blocks
        int gx = (blk - 9408) * 256 + threadIdx.x;
        if (gx < WG) {
            float af = (float)(2.0 * M_PI) * (float)gx / 640.0f;
            g_unit[gx * 2 + 0] = sinf(af);
            g_unit[gx * 2 + 1] = cosf(af);
        }
        return;
    }
    int gid = blk * 256 + threadIdx.x;     // 9408*256 == NB*3*NPIX/4 exact
    const int total = NB * 3 * NPIX / 4;
    float4 q0 = __ldg(reinterpret_cast<const float4*>(x) + gid);
    float4 q1 = make_float4(0.f, 0.f, 0.f, 0.f);
    if (gid + 1 < total) q1 = __ldg(reinterpret_cast<const float4*>(x) + gid + 1);
    float4 o; o.x = q0.y; o.y = q0.z; o.z = q0.w; o.w = q1.x;
    reinterpret_cast<float4*>(g_xs)[gid] = o;
}

// ---------------- K2: conv1 + maxpool, pair loads (no packing MOVs) ---------
__device__ __forceinline__ void loadrow(ull* P, const float* xrow, const float* xsrow) {
    longlong2 e01 = __ldg(reinterpret_cast<const longlong2*>(xrow));        // (0,1),(2,3)
    longlong2 e23 = __ldg(reinterpret_cast<const longlong2*>(xrow) + 1);    // (4,5),(6,7)
    longlong2 o01 = __ldg(reinterpret_cast<const longlong2*>(xsrow));       // (1,2),(3,4)
    ull       o2  = __ldg(reinterpret_cast<const ull*>(xsrow) + 2);         // (5,6)
    P[0] = (ull)e01.x; P[1] = (ull)o01.x; P[2] = (ull)e01.y; P[3] = (ull)o01.y;
    P[4] = (ull)e23.x; P[5] = o2;         P[6] = (ull)e23.y;
}

__global__ void __launch_bounds__(128) k_conv1_v4(const float* __restrict__ x,
                                                  const float* __restrict__ w,
                                                  const float* __restrict__ bia) {
    __shared__ ull  swd[456];
    __shared__ float sb[6];
    int tid = threadIdx.x;
    for (int i = tid; i < 450; i += 128) {
        int co = i / 75, r = i % 75;
        float ww = w[i];
        swd[r * 6 + co] = pk(ww, ww);
    }
    if (tid < 6) sb[tid] = bia[tid];
    __syncthreads();

    int b = blockIdx.y;
    int pos2 = blockIdx.x * 128 + tid;
    if (pos2 >= 55 * HP) return;
    int py = pos2 / 55, pxp = pos2 % 55;
    int px0 = 2 * pxp;
    size_t rowoff = (size_t)(2 * py) * IMG + 4 * pxp;
    const float* xb  = x    + (size_t)b * 3 * NPIX + rowoff;
    const float* xsb = g_xs + (size_t)b * 3 * NPIX + rowoff;

    ull acc[6][4];
    #pragma unroll
    for (int co = 0; co < 6; co++)
        #pragma unroll
        for (int q = 0; q < 4; q++) acc[co][q] = 0ull;

    #pragma unroll 1
    for (int ci = 0; ci < 3; ci++) {
        const float* xc  = xb  + (size_t)ci * NPIX;
        const float* xsc = xsb + (size_t)ci * NPIX;
        ull P[2][7];
        loadrow(P[0], xc, xsc);
        #pragma unroll
        for (int ky = 0; ky < 5; ky++) {
            loadrow(P[(ky + 1) & 1], xc + (ky + 1) * IMG, xsc + (ky + 1) * IMG);
            const ull* PA = P[ky & 1];
            const ull* PB = P[(ky + 1) & 1];
            const ull* wr = swd + (ci * 25 + ky * 5) * 6;
            #pragma unroll
            for (int kx = 0; kx < 5; kx++) {
                #pragma unroll
                for (int co = 0; co < 6; co++) {
                    ull wd = wr[kx * 6 + co];
                    fma2(acc[co][0], PA[kx],     wd);
                    fma2(acc[co][1], PB[kx],     wd);
                    fma2(acc[co][2], PA[kx + 2], wd);
                    fma2(acc[co][3], PB[kx + 2], wd);
                }
            }
        }
    }
    #pragma unroll
    for (int co = 0; co < 6; co++) {
        float2 u0 = unpk(acc[co][0]);
        float2 u1 = unpk(acc[co][1]);
        float2 u2 = unpk(acc[co][2]);
        float2 u3 = unpk(acc[co][3]);
        float2 m;
        m.x = fmaxf(fmaxf(u0.x, u0.y), fmaxf(u1.x, u1.y)) + sb[co];
        m.y = fmaxf(fmaxf(u2.x, u2.y), fmaxf(u3.x, u3.y)) + sb[co];
        *reinterpret_cast<float2*>(
            g_h1 + ((size_t)b * 6 + co) * (HP * HP) + (size_t)py * HP + px0) = m;
    }
}

// ---------------- K3: fused winsum + head + radii (per-batch block) ---------
__global__ void k_winsum_head(const float* __restrict__ w2, const float* __restrict__ b2,
                              const float* __restrict__ f1w, const float* __restrict__ f1b,
                              const float* __restrict__ f2w, const float* __restrict__ f2b,
                              float* __restrict__ outw) {
    int b = blockIdx.x, tid = threadIdx.x;
    __shared__ double sC[6][5][112];
    __shared__ double sS[150];
    __shared__ double sred[16][8];
    __shared__ double sfeat[16];
    __shared__ double sh[8];
    __shared__ float  slog[2];

    // column sums (identical order to previous k_winsum)
    for (int task = tid; task < 660; task += 128) {
        int c = task / 110, xcol = task % 110;
        const float* h = g_h1 + ((size_t)(b * 6 + c)) * (HP * HP);
        double s0 = 0.0, s1 = 0.0, s2 = 0.0, s3 = 0.0;
        #pragma unroll 1
        for (int y = 0; y < 104; y += 4) {
            s0 += (double)h[(y    ) * HP + xcol];
            s1 += (double)h[(y + 1) * HP + xcol];
            s2 += (double)h[(y + 2) * HP + xcol];
            s3 += (double)h[(y + 3) * HP + xcol];
        }
        s0 += (double)h[104 * HP + xcol];
        s1 += (double)h[105 * HP + xcol];
        double s = (s0 + s1) + (s2 + s3);
        sC[c][0][xcol] = s;
        #pragma unroll
        for (int ky = 1; ky < 5; ky++) {
            s += (double)h[(ky + 105) * HP + xcol] - (double)h[(ky - 1) * HP + xcol];
            sC[c][ky][xcol] = s;
        }
    }
    __syncthreads();

    // window sums (identical order)
    for (int task = tid; task < 150; task += 128) {
        int c = task / 25, r = task % 25;
        int ky = r / 5, kx = r % 5;
        const double* row = sC[c][ky];
        double s0 = 0.0, s1 = 0.0, s2 = 0.0, s3 = 0.0;
        int xx = kx;
        #pragma unroll 1
        for (; xx + 3 < kx + 106; xx += 4) {
            s0 += row[xx]; s1 += row[xx + 1]; s2 += row[xx + 2]; s3 += row[xx + 3];
        }
        for (; xx < kx + 106; xx++) s0 += row[xx];
        sS[task] = (s0 + s1) + (s2 + s3);
    }
    __syncthreads();

    // feat slice-reduce
    {
        int o = tid / 8, sl = tid % 8;
        double a = 0.0;
        for (int i = sl; i < 150; i += 8)
            a += (double)w2[o * 150 + i] * sS[i];
        sred[o][sl] = a;
    }
    __syncthreads();

    if (tid < 16) {
        double s = 0.0;
        #pragma unroll
        for (int k = 0; k < 8; k++) s += sred[tid][k];
        sfeat[tid] = s / 11236.0 + (double)b2[tid];
    }
    __syncthreads();

    if (tid < 8) {
        double acc = (double)f1b[tid];
        #pragma unroll
        for (int q = 0; q < 16; q++) acc += sfeat[q] * (double)f1w[tid * 16 + q];
        sh[tid] = acc > 0.0 ? acc : 0.0;
    }
    __syncthreads();

    if (tid < 2) {
        double acc = (double)f2b[tid];
        #pragma unroll
        for (int j = 0; j < 8; j++) acc += sh[j] * (double)f2w[tid * 8 + j];
        double s = 1.0 / (1.0 + exp(-acc));
        float wf = (float)(s * 5.0);
        outw[b * 2 + tid] = wf;
        float scaled = (tid == 0 ? 0.01f : 0.6f) * wf;
        slog[tid] = (float)log((double)scaled);
    }
    __syncthreads();

    float stf = slog[0], spf = slog[1];
    float dl = spf - stf;
    if (tid == 0) { g_startf[b] = stf; g_dlogf[b] = dl; }

    for (int gy = tid; gy < HG; gy += 128) {
        float t = (float)gy / 319.0f;
        g_radii[b * HG + gy] = expf(stf + dl * t);
    }
}

// ---------------- K4: grid sample, lane=angle, 64-bit pair gathers ----------
__global__ void __launch_bounds__(640) k_sample3(const float* __restrict__ x,
                                                 const float* __restrict__ lt,
                                                 float* __restrict__ out) {
    __shared__ float s_rad[10];
    __shared__ float s_acc[3][640];
    int b  = blockIdx.y;
    int py = blockIdx.x;
    int t  = threadIdx.x;

    if (t < 10) s_rad[t] = g_radii[b * HG + py * 10 + t];
    __syncthreads();

    float us = g_unit[t * 2 + 0];
    float uc = g_unit[t * 2 + 1];
    float l0 = lt[b * 2 + 0];
    float l1 = lt[b * 2 + 1];
    const ull* xp  = reinterpret_cast<const ull*>(x    + (size_t)b * 3 * NPIX);
    const ull* xsp = reinterpret_cast<const ull*>(g_xs + (size_t)b * 3 * NPIX);
    const int RP = NPIX / 2;      // pairs per channel
    const int WP = IMG / 2;       // pairs per row

    float a0 = 0.f, a1 = 0.f, a2 = 0.f;
    #pragma unroll 1
    for (int i = 0; i < 10; i++) {
        float r = s_rad[i];
        float gxx = r * us + l0;
        float gyy = r * uc + l1;
        float ix = ((gxx + 1.0f) * 224.0f - 1.0f) * 0.5f;
        float iy = ((gyy + 1.0f) * 224.0f - 1.0f) * 0.5f;
        float fx = floorf(ix), fy = floorf(iy);
        float wx = ix - fx,   wy = iy - fy;
        int x0 = min(max((int)fx, 0), 223);
        int x1 = min(max((int)fx + 1, 0), 223);
        int y0 = min(max((int)fy, 0), 223);
        int y1 = min(max((int)fy + 1, 0), 223);
        float w00 = (1.f - wx) * (1.f - wy);
        float w01 = wx * (1.f - wy);
        float w10 = (1.f - wx) * wy;
        float w11 = wx * wy;

        int xl = min(x0, 222);
        const ull* bp = (xl & 1) ? xsp : xp;
        int p0 = y0 * WP + (xl >> 1);
        int p1 = y1 * WP + (xl >> 1);
        bool hi0 = (x0 == 223);
        bool dup = (x1 == x0);

        #pragma unroll
        for (int c = 0; c < 3; c++) {
            float2 A = unpk(__ldg(bp + c * RP + p0));
            float2 Bv = unpk(__ldg(bp + c * RP + p1));
            float v00 = hi0 ? A.y : A.x;
            float v01 = dup ? v00 : A.y;
            float v10 = hi0 ? Bv.y : Bv.x;
            float v11 = dup ? v10 : Bv.y;
            float sv = w00 * v00 + w01 * v01 + w10 * v10 + w11 * v11;
            if (c == 0) a0 += sv;
            else if (c == 1) a1 += sv;
            else a2 += sv;
        }
    }
    s_acc[0][t] = a0;
    s_acc[1][t] = a1;
    s_acc[2][t] = a2;
    __syncthreads();

    if (t < 192) {
        int c = t / 64, pw = t % 64;
        const float* sp = &s_acc[c][pw * 10];
        float s = 0.f;
        #pragma unroll
        for (int j = 0; j < 10; j++) s += sp[j];
        out[(((size_t)b * 3 + c) * 32 + py) * 64 + pw] = s * 0.01f;
    }
}

// ---------------- launch ------------------------------------------------------
extern "C" void kernel_launch(void* const* d_in, const int* in_sizes, int n_in,
                              void* d_out, int out_size) {
    const float* x   = (const float*)d_in[0];
    const float* lt  = (const float*)d_in[1];
    const float* c1w = (const float*)d_in[2];
    const float* c1b = (const float*)d_in[3];
    const float* c2w = (const float*)d_in[4];
    const float* c2b = (const float*)d_in[5];
    const float* f1w = (const float*)d_in[6];
    const float* f1b = (const float*)d_in[7];
    const float* f2w = (const float*)d_in[8];
    const float* f2b = (const float*)d_in[9];
    float* out = (float*)d_out;

    k_shift_unit<<<9411, 256>>>(x);                                        // #1
    k_conv1_v4<<<dim3((55 * HP + 127) / 128, NB), 128>>>(x, c1w, c1b);     // #2
    k_winsum_head<<<NB, 128>>>(c2w, c2b, f1w, f1b, f2w, f2b,
                               out + 64 * 3 * 32 * 64);                    // #3
    k_sample3<<<dim3(32, NB), 640>>>(x, lt, out);                          // #4 -> profiled
}

// round 13
// speedup vs baseline: 1.2964x; 1.2964x over previous
#include <cuda_runtime.h>
#include <math.h>

#define NB 64
#define IMG 224
#define HP 110
#define NPIX (IMG*IMG)
#define HG 320
#define WG 640

typedef unsigned long long ull;

// ---------------- scratch ----------------------------------------------------
__device__ float  g_xs[(size_t)NB * 3 * NPIX];        // x shifted by one element
__device__ float  g_h1[(size_t)NB * 6 * HP * HP];
__device__ double g_S[NB * 6 * 25];
__device__ float  g_startf[NB], g_dlogf[NB];
__device__ float  g_radii[NB * HG];
__device__ float  g_unit[WG * 2];

// ---------------- f32x2 helpers ----------------------------------------------
__device__ __forceinline__ ull pk(float lo, float hi) {
    ull r; asm("mov.b64 %0,{%1,%2};" : "=l"(r) : "f"(lo), "f"(hi)); return r;
}
__device__ __forceinline__ float2 unpk(ull v) {
    float2 r; asm("mov.b64 {%0,%1},%2;" : "=f"(r.x), "=f"(r.y) : "l"(v)); return r;
}
__device__ __forceinline__ void fma2(ull& d, ull a, ull b) {
    asm("fma.rn.f32x2 %0,%1,%2,%0;" : "+l"(d) : "l"(a), "l"(b));
}

// ---------------- K1: xs[i] = x[i+1] shift + unit table ----------------------
__global__ void k_shift_unit(const float* __restrict__ x) {
    int blk = blockIdx.x;
    if (blk >= 9408) {                     // unit-table blocks
        int gx = (blk - 9408) * 256 + threadIdx.x;
        if (gx < WG) {
            float af = (float)(2.0 * M_PI) * (float)gx / 640.0f;
            g_unit[gx * 2 + 0] = sinf(af);
            g_unit[gx * 2 + 1] = cosf(af);
        }
        return;
    }
    int gid = blk * 256 + threadIdx.x;     // 9408*256 == NB*3*NPIX/4 exact
    const int total = NB * 3 * NPIX / 4;
    float4 q0 = __ldg(reinterpret_cast<const float4*>(x) + gid);
    float4 q1 = make_float4(0.f, 0.f, 0.f, 0.f);
    if (gid + 1 < total) q1 = __ldg(reinterpret_cast<const float4*>(x) + gid + 1);
    float4 o; o.x = q0.y; o.y = q0.z; o.z = q0.w; o.w = q1.x;
    reinterpret_cast<float4*>(g_xs)[gid] = o;
}

// ---------------- K2: conv1 + maxpool, pair loads (no packing MOVs) ---------
__device__ __forceinline__ void loadrow(ull* P, const float* xrow, const float* xsrow) {
    longlong2 e01 = __ldg(reinterpret_cast<const longlong2*>(xrow));
    longlong2 e23 = __ldg(reinterpret_cast<const longlong2*>(xrow) + 1);
    longlong2 o01 = __ldg(reinterpret_cast<const longlong2*>(xsrow));
    ull       o2  = __ldg(reinterpret_cast<const ull*>(xsrow) + 2);
    P[0] = (ull)e01.x; P[1] = (ull)o01.x; P[2] = (ull)e01.y; P[3] = (ull)o01.y;
    P[4] = (ull)e23.x; P[5] = o2;         P[6] = (ull)e23.y;
}

__global__ void __launch_bounds__(128) k_conv1_v4(const float* __restrict__ x,
                                                  const float* __restrict__ w,
                                                  const float* __restrict__ bia) {
    __shared__ ull  swd[456];
    __shared__ float sb[6];
    int tid = threadIdx.x;
    for (int i = tid; i < 450; i += 128) {
        int co = i / 75, r = i % 75;
        float ww = w[i];
        swd[r * 6 + co] = pk(ww, ww);
    }
    if (tid < 6) sb[tid] = bia[tid];
    __syncthreads();

    int b = blockIdx.y;
    int pos2 = blockIdx.x * 128 + tid;
    if (pos2 >= 55 * HP) return;
    int py = pos2 / 55, pxp = pos2 % 55;
    int px0 = 2 * pxp;
    size_t rowoff = (size_t)(2 * py) * IMG + 4 * pxp;
    const float* xb  = x    + (size_t)b * 3 * NPIX + rowoff;
    const float* xsb = g_xs + (size_t)b * 3 * NPIX + rowoff;

    ull acc[6][4];
    #pragma unroll
    for (int co = 0; co < 6; co++)
        #pragma unroll
        for (int q = 0; q < 4; q++) acc[co][q] = 0ull;

    #pragma unroll 1
    for (int ci = 0; ci < 3; ci++) {
        const float* xc  = xb  + (size_t)ci * NPIX;
        const float* xsc = xsb + (size_t)ci * NPIX;
        ull P[2][7];
        loadrow(P[0], xc, xsc);
        #pragma unroll
        for (int ky = 0; ky < 5; ky++) {
            loadrow(P[(ky + 1) & 1], xc + (ky + 1) * IMG, xsc + (ky + 1) * IMG);
            const ull* PA = P[ky & 1];
            const ull* PB = P[(ky + 1) & 1];
            const ull* wr = swd + (ci * 25 + ky * 5) * 6;
            #pragma unroll
            for (int kx = 0; kx < 5; kx++) {
                #pragma unroll
                for (int co = 0; co < 6; co++) {
                    ull wd = wr[kx * 6 + co];
                    fma2(acc[co][0], PA[kx],     wd);
                    fma2(acc[co][1], PB[kx],     wd);
                    fma2(acc[co][2], PA[kx + 2], wd);
                    fma2(acc[co][3], PB[kx + 2], wd);
                }
            }
        }
    }
    #pragma unroll
    for (int co = 0; co < 6; co++) {
        float2 u0 = unpk(acc[co][0]);
        float2 u1 = unpk(acc[co][1]);
        float2 u2 = unpk(acc[co][2]);
        float2 u3 = unpk(acc[co][3]);
        float2 m;
        m.x = fmaxf(fmaxf(u0.x, u0.y), fmaxf(u1.x, u1.y)) + sb[co];
        m.y = fmaxf(fmaxf(u2.x, u2.y), fmaxf(u3.x, u3.y)) + sb[co];
        *reinterpret_cast<float2*>(
            g_h1 + ((size_t)b * 6 + co) * (HP * HP) + (size_t)py * HP + px0) = m;
    }
}

// ---------------- K3: winsum, chunk-parallel (double) ------------------------
__global__ void __launch_bounds__(512) k_winsum3() {
    int bc = blockIdx.x;                  // b*6 + c
    int tid = threadIdx.x;
    __shared__ double sP[4][112];         // chunk partials of full column sum
    __shared__ double sC[5][112];         // 5 shifted column sums
    __shared__ double sW[25][4];          // window-sum chunk partials

    const float* h = g_h1 + (size_t)bc * HP * HP;
    int chunk = tid >> 7, xcol = tid & 127;

    if (xcol < HP) {
        int y0 = chunk * 28, y1 = min(y0 + 28, HP);
        double s = 0.0;
        for (int y = y0; y < y1; y++) s += (double)h[y * HP + xcol];
        sP[chunk][xcol] = s;
    }
    __syncthreads();

    if (tid < HP) {
        double F = (sP[0][tid] + sP[1][tid]) + (sP[2][tid] + sP[3][tid]);
        double b0 = (double)h[0 * HP + tid], b1 = (double)h[1 * HP + tid];
        double b2 = (double)h[2 * HP + tid], b3 = (double)h[3 * HP + tid];
        double e0 = (double)h[106 * HP + tid], e1 = (double)h[107 * HP + tid];
        double e2 = (double)h[108 * HP + tid], e3 = (double)h[109 * HP + tid];
        sC[0][tid] = F - e0 - e1 - e2 - e3;
        sC[1][tid] = F - b0 - e1 - e2 - e3;
        sC[2][tid] = F - b0 - b1 - e2 - e3;
        sC[3][tid] = F - b0 - b1 - b2 - e3;
        sC[4][tid] = F - b0 - b1 - b2 - b3;
    }
    __syncthreads();

    if (tid < 100) {
        int r = tid >> 2, ch = tid & 3;
        int ky = r / 5, kx = r % 5;
        int x0 = kx + ch * 27, x1 = kx + min(ch * 27 + 27, 106);
        double s = 0.0;
        for (int xx = x0; xx < x1; xx++) s += sC[ky][xx];
        sW[r][ch] = s;
    }
    __syncthreads();

    if (tid < 25)
        g_S[bc * 25 + tid] = (sW[tid][0] + sW[tid][1]) + (sW[tid][2] + sW[tid][3]);
}

// ---------------- K4: head (parallel) + radii --------------------------------
__global__ void k_head2(const float* __restrict__ w2, const float* __restrict__ b2,
                        const float* __restrict__ f1w, const float* __restrict__ f1b,
                        const float* __restrict__ f2w, const float* __restrict__ f2b,
                        float* __restrict__ outw) {
    int b = blockIdx.x, tid = threadIdx.x;
    __shared__ double sred[16][8];
    __shared__ double sfeat[16];
    __shared__ double sh[8];
    __shared__ float  slog[2];

    const double* Sb = g_S + b * 150;
    int o = tid / 8, sl = tid % 8;
    double a = 0.0;
    for (int i = sl; i < 150; i += 8)
        a += (double)w2[o * 150 + i] * Sb[i];
    sred[o][sl] = a;
    __syncthreads();

    if (tid < 16) {
        double s = 0.0;
        #pragma unroll
        for (int k = 0; k < 8; k++) s += sred[tid][k];
        sfeat[tid] = s / 11236.0 + (double)b2[tid];
    }
    __syncthreads();

    if (tid < 8) {
        double acc = (double)f1b[tid];
        #pragma unroll
        for (int q = 0; q < 16; q++) acc += sfeat[q] * (double)f1w[tid * 16 + q];
        sh[tid] = acc > 0.0 ? acc : 0.0;
    }
    __syncthreads();

    if (tid < 2) {
        double acc = (double)f2b[tid];
        #pragma unroll
        for (int j = 0; j < 8; j++) acc += sh[j] * (double)f2w[tid * 8 + j];
        double s = 1.0 / (1.0 + exp(-acc));
        float wf = (float)(s * 5.0);
        outw[b * 2 + tid] = wf;
        float scaled = (tid == 0 ? 0.01f : 0.6f) * wf;
        slog[tid] = (float)log((double)scaled);
    }
    __syncthreads();

    float stf = slog[0], spf = slog[1];
    float dl = spf - stf;
    if (tid == 0) { g_startf[b] = stf; g_dlogf[b] = dl; }

    for (int gy = tid; gy < HG; gy += 128) {
        float t = (float)gy / 319.0f;
        g_radii[b * HG + gy] = expf(stf + dl * t);
    }
}

// ---------------- K5: grid sample, lane=angle, 64-bit pair gathers ----------
__global__ void __launch_bounds__(640) k_sample3(const float* __restrict__ x,
                                                 const float* __restrict__ lt,
                                                 float* __restrict__ out) {
    __shared__ float s_rad[10];
    __shared__ float s_acc[3][640];
    int b  = blockIdx.y;
    int py = blockIdx.x;
    int t  = threadIdx.x;

    if (t < 10) s_rad[t] = g_radii[b * HG + py * 10 + t];
    __syncthreads();

    float us = g_unit[t * 2 + 0];
    float uc = g_unit[t * 2 + 1];
    float l0 = lt[b * 2 + 0];
    float l1 = lt[b * 2 + 1];
    const ull* xp  = reinterpret_cast<const ull*>(x    + (size_t)b * 3 * NPIX);
    const ull* xsp = reinterpret_cast<const ull*>(g_xs + (size_t)b * 3 * NPIX);
    const int RP = NPIX / 2;
    const int WP = IMG / 2;

    float a0 = 0.f, a1 = 0.f, a2 = 0.f;
    #pragma unroll 1
    for (int i = 0; i < 10; i++) {
        float r = s_rad[i];
        float gxx = r * us + l0;
        float gyy = r * uc + l1;
        float ix = ((gxx + 1.0f) * 224.0f - 1.0f) * 0.5f;
        float iy = ((gyy + 1.0f) * 224.0f - 1.0f) * 0.5f;
        float fx = floorf(ix), fy = floorf(iy);
        float wx = ix - fx,   wy = iy - fy;
        int x0 = min(max((int)fx, 0), 223);
        int x1 = min(max((int)fx + 1, 0), 223);
        int y0 = min(max((int)fy, 0), 223);
        int y1 = min(max((int)fy + 1, 0), 223);
        float w00 = (1.f - wx) * (1.f - wy);
        float w01 = wx * (1.f - wy);
        float w10 = (1.f - wx) * wy;
        float w11 = wx * wy;

        int xl = min(x0, 222);
        const ull* bp = (xl & 1) ? xsp : xp;
        int p0 = y0 * WP + (xl >> 1);
        int p1 = y1 * WP + (xl >> 1);
        bool hi0 = (x0 == 223);
        bool dup = (x1 == x0);

        #pragma unroll
        for (int c = 0; c < 3; c++) {
            float2 A = unpk(__ldg(bp + c * RP + p0));
            float2 Bv = unpk(__ldg(bp + c * RP + p1));
            float v00 = hi0 ? A.y : A.x;
            float v01 = dup ? v00 : A.y;
            float v10 = hi0 ? Bv.y : Bv.x;
            float v11 = dup ? v10 : Bv.y;
            float sv = w00 * v00 + w01 * v01 + w10 * v10 + w11 * v11;
            if (c == 0) a0 += sv;
            else if (c == 1) a1 += sv;
            else a2 += sv;
        }
    }
    s_acc[0][t] = a0;
    s_acc[1][t] = a1;
    s_acc[2][t] = a2;
    __syncthreads();

    if (t < 192) {
        int c = t / 64, pw = t % 64;
        const float* sp = &s_acc[c][pw * 10];
        float s = 0.f;
        #pragma unroll
        for (int j = 0; j < 10; j++) s += sp[j];
        out[(((size_t)b * 3 + c) * 32 + py) * 64 + pw] = s * 0.01f;
    }
}

// ---------------- launch ------------------------------------------------------
extern "C" void kernel_launch(void* const* d_in, const int* in_sizes, int n_in,
                              void* d_out, int out_size) {
    const float* x   = (const float*)d_in[0];
    const float* lt  = (const float*)d_in[1];
    const float* c1w = (const float*)d_in[2];
    const float* c1b = (const float*)d_in[3];
    const float* c2w = (const float*)d_in[4];
    const float* c2b = (const float*)d_in[5];
    const float* f1w = (const float*)d_in[6];
    const float* f1b = (const float*)d_in[7];
    const float* f2w = (const float*)d_in[8];
    const float* f2b = (const float*)d_in[9];
    float* out = (float*)d_out;

    k_shift_unit<<<9411, 256>>>(x);                                        // #1
    k_conv1_v4<<<dim3((55 * HP + 127) / 128, NB), 128>>>(x, c1w, c1b);     // #2
    k_winsum3<<<NB * 6, 512>>>();                                          // #3
    k_head2<<<NB, 128>>>(c2w, c2b, f1w, f1b, f2w, f2b,
                         out + 64 * 3 * 32 * 64);                          // #4 -> profiled
    k_sample3<<<dim3(32, NB), 640>>>(x, lt, out);                          // #5
}